// round 4
// baseline (speedup 1.0000x reference)
#include <cuda_runtime.h>

// ---------------------------------------------------------------------------
// Performer attention. Fixed shapes: B=4, S=4096, Dm=1024, H=16, Dh=64, R=256
// fp32 baseline: 4 SGEMMs + fused FAVOR+ feature kernels + batched linear
// attention contractions. All scratch in __device__ globals (no allocations).
// ---------------------------------------------------------------------------

#define B_    4
#define S_    4096
#define DM    1024
#define H_    16
#define DH    64
#define RR    256
#define MROWS (B_*S_)        // 16384
#define NROWS (B_*S_*H_)     // 262144
#define BH    (B_*H_)        // 64
#define SPLIT 8
#define SCH   (S_/SPLIT)     // 512

#define RATIO 0.0625f                 // 1/sqrt(R)
#define CNORM 0.35355339059327373f    // Dh^{-1/4}

// ------------------------------ scratch ------------------------------------
__device__ float g_q[MROWS*DM];
__device__ float g_k[MROWS*DM];
__device__ float g_v[MROWS*DM];
__device__ float g_att[MROWS*DM];
__device__ float g_qhat[NROWS*RR];         // q_hat
__device__ float g_u[NROWS*RR];            // exp(dh - diag) for keys
__device__ float g_den[NROWS];             // denom per (b,s,h)
__device__ float g_kvp[SPLIT*BH*RR*DH];    // kv split-S partials
__device__ float g_kvf[BH*RR*DH];          // final kv
__device__ float g_u1p[SPLIT*BH*RR];
__device__ float g_v1p[SPLIT*BH*DH];
__device__ float g_k1[BH*RR];
__device__ float g_v1[BH*DH];
__device__ float g_kmax;

// ------------------------- FMA-pipe exp (no MUFU) --------------------------
__device__ __forceinline__ float fexp(float x)
{
    x = fminf(fmaxf(x, -87.0f), 87.0f);
    float z = x * 1.4426950408889634f;
    float t = z + 12582912.0f;                  // round-to-nearest-int trick
    int   n = __float_as_int(t) - 0x4B400000;
    float f = z - (t - 12582912.0f);            // frac in [-0.5, 0.5]
    float p = 1.3333558e-3f;
    p = fmaf(p, f, 9.6181291e-3f);
    p = fmaf(p, f, 5.5504109e-2f);
    p = fmaf(p, f, 2.4022651e-1f);
    p = fmaf(p, f, 6.9314718e-1f);
    p = fmaf(p, f, 1.0f);
    return p * __int_as_float((n + 127) << 23);
}

__device__ __forceinline__ void atomicMaxF(float* addr, float v)
{
    int* ia = (int*)addr;
    int old = *ia;
    while (__int_as_float(old) < v) {
        int assumed = old;
        old = atomicCAS(ia, assumed, __float_as_int(v));
        if (old == assumed) break;
    }
}

__global__ void k_init() { g_kmax = -3.0e38f; }

// --------------------- SGEMM M=16384, N=K=1024, + bias ---------------------
// C[M,N] = A[M,K] @ B[K,N] + bias[N]; 128x128 tile, 8x8 per thread, 256 thr.
__global__ __launch_bounds__(256)
void k_sgemm_bias(const float* __restrict__ A, const float* __restrict__ Bm,
                  const float* __restrict__ bias, float* __restrict__ C)
{
    __shared__ float As[8][128];
    __shared__ float Bs[8][128];
    const int tid  = threadIdx.x;
    const int bx   = blockIdx.x, by = blockIdx.y;
    const int trow = (tid >> 4) * 8;
    const int tcol = (tid & 15) * 8;
    const int aRow = tid >> 1,  aCol = (tid & 1) * 4;
    const int bRow = tid >> 5,  bCol = (tid & 31) * 4;
    const float* Ap = A  + (by * 128 + aRow) * DM + aCol;
    const float* Bp = Bm + bRow * DM + bx * 128 + bCol;

    float acc[8][8] = {};
    float4 av = *(const float4*)Ap;
    float4 bv = *(const float4*)Bp;

    for (int k0 = 0; k0 < DM; k0 += 8) {
        As[aCol + 0][aRow] = av.x;
        As[aCol + 1][aRow] = av.y;
        As[aCol + 2][aRow] = av.z;
        As[aCol + 3][aRow] = av.w;
        *(float4*)&Bs[bRow][bCol] = bv;
        __syncthreads();
        if (k0 + 8 < DM) {
            av = *(const float4*)(Ap + k0 + 8);
            bv = *(const float4*)(Bp + (k0 + 8) * DM);
        }
        #pragma unroll
        for (int k = 0; k < 8; k++) {
            float a0[8], b0[8];
            *(float4*)&a0[0] = *(const float4*)&As[k][trow];
            *(float4*)&a0[4] = *(const float4*)&As[k][trow + 4];
            *(float4*)&b0[0] = *(const float4*)&Bs[k][tcol];
            *(float4*)&b0[4] = *(const float4*)&Bs[k][tcol + 4];
            #pragma unroll
            for (int i = 0; i < 8; i++)
                #pragma unroll
                for (int j = 0; j < 8; j++)
                    acc[i][j] = fmaf(a0[i], b0[j], acc[i][j]);
        }
        __syncthreads();
    }
    #pragma unroll
    for (int i = 0; i < 8; i++) {
        float* Cp = C + (by * 128 + trow + i) * DM + bx * 128 + tcol;
        #pragma unroll
        for (int j = 0; j < 8; j += 4) {
            float4 o;
            o.x = acc[i][j + 0] + bias[bx * 128 + tcol + j + 0];
            o.y = acc[i][j + 1] + bias[bx * 128 + tcol + j + 1];
            o.z = acc[i][j + 2] + bias[bx * 128 + tcol + j + 2];
            o.w = acc[i][j + 3] + bias[bx * 128 + tcol + j + 3];
            *(float4*)(Cp + j) = o;
        }
    }
}

// ------------------- FAVOR+ feature kernel (q or k) -------------------------
// X viewed as [NROWS][64] (row n = (b*S+s)*H+h is contiguous 64 floats).
// dh[r] = (CNORM*x) . proj[r];  diag = 0.0625*|x|^2.
// IS_Q: out = RATIO*(exp(dh - diag - rowmax(dh)) + 1e-4); denom = out . k1[bh]
// !IS_Q: out = exp(dh - diag); atomic-max of dh into g_kmax.
// 256 thr/block; warp handles 4 rows per step, 16 steps -> 512 rows/block.
#define FEAT_SMEM ((64*256 + 8*4*64) * 4)

template <bool IS_Q>
__global__ __launch_bounds__(256)
void k_feat(const float* __restrict__ X, const float* __restrict__ proj,
            float* __restrict__ out, const float* __restrict__ k1,
            float* __restrict__ den)
{
    extern __shared__ float sm[];
    float* projT = sm;             // [64 k][256 r], scaled by CNORM
    float* sq    = sm + 64 * 256;  // [8 warps][4 rows][64]
    const int tid = threadIdx.x;
    const int w = tid >> 5, l = tid & 31;

    for (int i = tid; i < 64 * 256; i += 256) {
        int k = i >> 8, r = i & 255;
        projT[i] = CNORM * proj[r * 64 + k];
    }
    __syncthreads();

    const float4* pT = (const float4*)projT;  // pT[k*64 + j] = projT[k][4j..]
    float* sqw = sq + w * 4 * 64;
    float wmax = -3.0e38f;
    const int jrow = l >> 3;
    const int off  = (l & 7) * 8;
    const int base = blockIdx.x * 512 + w * 64;

    for (int it = 0; it < 16; it++) {
        const int n0 = base + it * 4;
        const float* xp = X + (n0 + jrow) * 64 + off;
        float4 xa = *(const float4*)xp;
        float4 xb = *(const float4*)(xp + 4);
        float ss = xa.x*xa.x + xa.y*xa.y + xa.z*xa.z + xa.w*xa.w
                 + xb.x*xb.x + xb.y*xb.y + xb.z*xb.z + xb.w*xb.w;
        ss += __shfl_xor_sync(0xffffffffu, ss, 1);
        ss += __shfl_xor_sync(0xffffffffu, ss, 2);
        ss += __shfl_xor_sync(0xffffffffu, ss, 4);
        float diagl = 0.0625f * ss;
        float diag[4];
        #pragma unroll
        for (int j = 0; j < 4; j++)
            diag[j] = __shfl_sync(0xffffffffu, diagl, j * 8);

        __syncwarp();
        *(float4*)&sqw[jrow * 64 + off]     = xa;
        *(float4*)&sqw[jrow * 64 + off + 4] = xb;
        __syncwarp();

        // lane l owns r = 4l..4l+3 (a0) and 128+4l..128+4l+3 (a1), 4 rows.
        float4 a0[4] = {}, a1[4] = {};
        #pragma unroll 2
        for (int k = 0; k < 64; k++) {
            float4 p0 = pT[k * 64 + l];
            float4 p1 = pT[k * 64 + 32 + l];
            #pragma unroll
            for (int j = 0; j < 4; j++) {
                float qk = sqw[j * 64 + k];
                a0[j].x = fmaf(qk, p0.x, a0[j].x);
                a0[j].y = fmaf(qk, p0.y, a0[j].y);
                a0[j].z = fmaf(qk, p0.z, a0[j].z);
                a0[j].w = fmaf(qk, p0.w, a0[j].w);
                a1[j].x = fmaf(qk, p1.x, a1[j].x);
                a1[j].y = fmaf(qk, p1.y, a1[j].y);
                a1[j].z = fmaf(qk, p1.z, a1[j].z);
                a1[j].w = fmaf(qk, p1.w, a1[j].w);
            }
        }
        #pragma unroll
        for (int j = 0; j < 4; j++) {
            const int n = n0 + j;
            float* op = out + n * 256 + 4 * l;
            float lm = fmaxf(fmaxf(fmaxf(a0[j].x, a0[j].y), fmaxf(a0[j].z, a0[j].w)),
                             fmaxf(fmaxf(a1[j].x, a1[j].y), fmaxf(a1[j].z, a1[j].w)));
            if (IS_Q) {
                #pragma unroll
                for (int o = 16; o > 0; o >>= 1)
                    lm = fmaxf(lm, __shfl_xor_sync(0xffffffffu, lm, o));
                const float sub = diag[j] + lm;
                float4 w0, w1;
                w0.x = RATIO * (fexp(a0[j].x - sub) + 1e-4f);
                w0.y = RATIO * (fexp(a0[j].y - sub) + 1e-4f);
                w0.z = RATIO * (fexp(a0[j].z - sub) + 1e-4f);
                w0.w = RATIO * (fexp(a0[j].w - sub) + 1e-4f);
                w1.x = RATIO * (fexp(a1[j].x - sub) + 1e-4f);
                w1.y = RATIO * (fexp(a1[j].y - sub) + 1e-4f);
                w1.z = RATIO * (fexp(a1[j].z - sub) + 1e-4f);
                w1.w = RATIO * (fexp(a1[j].w - sub) + 1e-4f);
                *(float4*)op         = w0;
                *(float4*)(op + 128) = w1;
                // denom = qhat_row . k1[bh]
                const int bh = ((n >> 16) << 4) | (n & 15);   // b*16+h
                const float* kp = k1 + bh * 256 + 4 * l;
                float4 c0 = *(const float4*)kp;
                float4 c1 = *(const float4*)(kp + 128);
                float dp = w0.x*c0.x + w0.y*c0.y + w0.z*c0.z + w0.w*c0.w
                         + w1.x*c1.x + w1.y*c1.y + w1.z*c1.z + w1.w*c1.w;
                #pragma unroll
                for (int o = 16; o > 0; o >>= 1)
                    dp += __shfl_xor_sync(0xffffffffu, dp, o);
                if (l == 0) den[n] = dp;
            } else {
                wmax = fmaxf(wmax, lm);
                const float sub = diag[j];
                float4 w0, w1;
                w0.x = fexp(a0[j].x - sub);
                w0.y = fexp(a0[j].y - sub);
                w0.z = fexp(a0[j].z - sub);
                w0.w = fexp(a0[j].w - sub);
                w1.x = fexp(a1[j].x - sub);
                w1.y = fexp(a1[j].y - sub);
                w1.z = fexp(a1[j].z - sub);
                w1.w = fexp(a1[j].w - sub);
                *(float4*)op         = w0;
                *(float4*)(op + 128) = w1;
            }
        }
    }
    if (!IS_Q) {
        #pragma unroll
        for (int o = 16; o > 0; o >>= 1)
            wmax = fmaxf(wmax, __shfl_xor_sync(0xffffffffu, wmax, o));
        __syncthreads();                // all warps done reading projT
        if (l == 0) sm[w] = wmax;
        __syncthreads();
        if (tid == 0) {
            float m = sm[0];
            #pragma unroll
            for (int i = 1; i < 8; i++) m = fmaxf(m, sm[i]);
            atomicMaxF(&g_kmax, m);
        }
    }
}

// --------- kv partials: per (bh, S-chunk) compute u^T @ v [256 x 64] --------
// Also accumulates column sums u1[r], v1[v] for the chunk.
__global__ __launch_bounds__(256)
void k_kv()
{
    __shared__ float Us[16][256];
    __shared__ float Vs[16][64];
    const int bh = blockIdx.x, c = blockIdx.y;
    const int b = bh >> 4, h = bh & 15;
    const int tid = threadIdx.x;
    const int ls = tid >> 4, lr = (tid & 15) * 16;
    const int lv = (tid & 15) * 4;
    const int tr = (tid >> 3) * 8, tv = (tid & 7) * 8;
    const float* ub = g_u + ((b * S_ + c * SCH) * H_ + h) * RR;
    const float* vb = g_v + (b * S_ + c * SCH) * DM + h * DH;

    float acc[8][8] = {};
    float uacc = 0.f, vacc = 0.f;
    for (int s0 = 0; s0 < SCH; s0 += 16) {
        const float* up = ub + (s0 + ls) * (H_ * RR) + lr;
        *(float4*)&Us[ls][lr]      = *(const float4*)(up);
        *(float4*)&Us[ls][lr + 4]  = *(const float4*)(up + 4);
        *(float4*)&Us[ls][lr + 8]  = *(const float4*)(up + 8);
        *(float4*)&Us[ls][lr + 12] = *(const float4*)(up + 12);
        *(float4*)&Vs[ls][lv] = *(const float4*)(vb + (s0 + ls) * DM + lv);
        __syncthreads();
        #pragma unroll
        for (int s = 0; s < 16; s++) {
            float ua[8], va[8];
            *(float4*)&ua[0] = *(const float4*)&Us[s][tr];
            *(float4*)&ua[4] = *(const float4*)&Us[s][tr + 4];
            *(float4*)&va[0] = *(const float4*)&Vs[s][tv];
            *(float4*)&va[4] = *(const float4*)&Vs[s][tv + 4];
            #pragma unroll
            for (int i = 0; i < 8; i++)
                #pragma unroll
                for (int j = 0; j < 8; j++)
                    acc[i][j] = fmaf(ua[i], va[j], acc[i][j]);
            uacc += Us[s][tid];
            if (tid < 64) vacc += Vs[s][tid];
        }
        __syncthreads();
    }
    const int pb = c * BH + bh;
    float* kp = g_kvp + pb * (RR * DH);
    #pragma unroll
    for (int i = 0; i < 8; i++) {
        *(float4*)&kp[(tr + i) * DH + tv]     = *(float4*)&acc[i][0];
        *(float4*)&kp[(tr + i) * DH + tv + 4] = *(float4*)&acc[i][4];
    }
    g_u1p[pb * RR + tid] = uacc;
    if (tid < 64) g_v1p[pb * DH + tid] = vacc;
}

// k1 = a*sum_s u + ratio*1e-4*S ; v1 = sum_s v (reduce split partials)
__global__ void k_red()
{
    const int bh = blockIdx.x, t = threadIdx.x;
    const float a = RATIO * fexp(-g_kmax);
    float s = 0.f;
    #pragma unroll
    for (int c = 0; c < SPLIT; c++) s += g_u1p[(c * BH + bh) * RR + t];
    g_k1[bh * RR + t] = a * s + RATIO * 1e-4f * (float)S_;
    if (t < DH) {
        float vs = 0.f;
        #pragma unroll
        for (int c = 0; c < SPLIT; c++) vs += g_v1p[(c * BH + bh) * DH + t];
        g_v1[bh * DH + t] = vs;
    }
}

// kv_final = a * sum_c kvp + ratio*1e-4 * v1[v]
__global__ void k_kvred()
{
    const int bh = blockIdx.x, r = blockIdx.y, v = threadIdx.x;
    const float a = RATIO * fexp(-g_kmax);
    float s = 0.f;
    #pragma unroll
    for (int c = 0; c < SPLIT; c++)
        s += g_kvp[((c * BH + bh) * RR + r) * DH + v];
    g_kvf[(bh * RR + r) * DH + v] = a * s + RATIO * 1e-4f * g_v1[bh * DH + v];
}

// ----- attention out: per (bh, s-chunk 128): qhat[128,256] @ kvf[256,64] ----
// then divide by denom and store as [bs][h*64+v] for the final GEMM.
__global__ __launch_bounds__(256)
void k_att()
{
    __shared__ float As[16][128];   // [k][s]
    __shared__ float Bs[16][64];    // [k][v]
    const int bh = blockIdx.x, sc = blockIdx.y;
    const int b = bh >> 4, h = bh & 15;
    const int tid = threadIdx.x;
    const int srow = tid >> 1, kcol = (tid & 1) * 8;
    const int krow = tid >> 4, vcol = (tid & 15) * 4;
    const int ts = (tid >> 3) * 4, tv = (tid & 7) * 8;
    const int s_base = sc * 128;
    const float* qb  = g_qhat + ((b * S_ + s_base) * H_ + h) * RR;
    const float* kvb = g_kvf + bh * (RR * DH);

    float acc[4][8] = {};
    for (int k0 = 0; k0 < RR; k0 += 16) {
        const float* qp = qb + srow * (H_ * RR) + k0 + kcol;
        float4 qa = *(const float4*)qp;
        float4 qc = *(const float4*)(qp + 4);
        As[kcol + 0][srow] = qa.x;
        As[kcol + 1][srow] = qa.y;
        As[kcol + 2][srow] = qa.z;
        As[kcol + 3][srow] = qa.w;
        As[kcol + 4][srow] = qc.x;
        As[kcol + 5][srow] = qc.y;
        As[kcol + 6][srow] = qc.z;
        As[kcol + 7][srow] = qc.w;
        *(float4*)&Bs[krow][vcol] = *(const float4*)(kvb + (k0 + krow) * DH + vcol);
        __syncthreads();
        #pragma unroll
        for (int k = 0; k < 16; k++) {
            float a4[4], b8[8];
            a4[0] = As[k][ts + 0];
            a4[1] = As[k][ts + 1];
            a4[2] = As[k][ts + 2];
            a4[3] = As[k][ts + 3];
            *(float4*)&b8[0] = *(const float4*)&Bs[k][tv];
            *(float4*)&b8[4] = *(const float4*)&Bs[k][tv + 4];
            #pragma unroll
            for (int i = 0; i < 4; i++)
                #pragma unroll
                for (int j = 0; j < 8; j++)
                    acc[i][j] = fmaf(a4[i], b8[j], acc[i][j]);
        }
        __syncthreads();
    }
    #pragma unroll
    for (int i = 0; i < 4; i++) {
        const int s = s_base + ts + i;
        const int n = (b * S_ + s) * H_ + h;
        const float inv = 1.0f / g_den[n];
        float* op = g_att + (b * S_ + s) * DM + h * DH + tv;
        float4 o0, o1;
        o0.x = acc[i][0] * inv; o0.y = acc[i][1] * inv;
        o0.z = acc[i][2] * inv; o0.w = acc[i][3] * inv;
        o1.x = acc[i][4] * inv; o1.y = acc[i][5] * inv;
        o1.z = acc[i][6] * inv; o1.w = acc[i][7] * inv;
        *(float4*)op       = o0;
        *(float4*)(op + 4) = o1;
    }
}

// ---------------------------------------------------------------------------
extern "C" void kernel_launch(void* const* d_in, const int* in_sizes, int n_in,
                              void* d_out, int out_size)
{
    const float* query = (const float*)d_in[0];
    const float* key   = (const float*)d_in[1];
    const float* value = (const float*)d_in[2];
    const float* Wq    = (const float*)d_in[3];
    const float* bq    = (const float*)d_in[4];
    const float* Wk    = (const float*)d_in[5];
    const float* bk    = (const float*)d_in[6];
    const float* Wv    = (const float*)d_in[7];
    const float* bv    = (const float*)d_in[8];
    const float* Wo    = (const float*)d_in[9];
    const float* bo    = (const float*)d_in[10];
    const float* proj  = (const float*)d_in[11];
    float* out = (float*)d_out;

    void *pq, *pk, *pv, *pa, *pqh, *pu, *pk1, *pden;
    cudaGetSymbolAddress(&pq,  g_q);
    cudaGetSymbolAddress(&pk,  g_k);
    cudaGetSymbolAddress(&pv,  g_v);
    cudaGetSymbolAddress(&pa,  g_att);
    cudaGetSymbolAddress(&pqh, g_qhat);
    cudaGetSymbolAddress(&pu,  g_u);
    cudaGetSymbolAddress(&pk1, g_k1);
    cudaGetSymbolAddress(&pden, g_den);

    cudaFuncSetAttribute(k_feat<true>,  cudaFuncAttributeMaxDynamicSharedMemorySize, FEAT_SMEM);
    cudaFuncSetAttribute(k_feat<false>, cudaFuncAttributeMaxDynamicSharedMemorySize, FEAT_SMEM);

    const dim3 gg(DM / 128, MROWS / 128);   // (8, 128)

    k_init<<<1, 1>>>();
    k_sgemm_bias<<<gg, 256>>>(query, Wq, bq, (float*)pq);
    k_sgemm_bias<<<gg, 256>>>(key,   Wk, bk, (float*)pk);
    k_sgemm_bias<<<gg, 256>>>(value, Wv, bv, (float*)pv);

    // key path first (global max + k1 needed before the fused q/denom kernel)
    k_feat<false><<<NROWS / 512, 256, FEAT_SMEM>>>((const float*)pk, proj,
                                                   (float*)pu, nullptr, nullptr);
    k_kv<<<dim3(BH, SPLIT), 256>>>();
    k_red<<<BH, 256>>>();
    k_kvred<<<dim3(BH, RR), DH>>>();

    k_feat<true><<<NROWS / 512, 256, FEAT_SMEM>>>((const float*)pq, proj,
                                                  (float*)pqh, (const float*)pk1,
                                                  (float*)pden);
    k_att<<<dim3(BH, S_ / 128), 256>>>();
    k_sgemm_bias<<<gg, 256>>>((const float*)pa, Wo, bo, out);
}

// round 6
// speedup vs baseline: 1.7348x; 1.7348x over previous
#include <cuda_runtime.h>
#include <cuda_bf16.h>
#include <cstdint>

// ---------------------------------------------------------------------------
// Performer attention. Fixed shapes: B=4, S=4096, Dm=1024, H=16, Dh=64, R=256
// Big GEMMs: split-bf16 (hi/lo) on mma.sync HMMA (compute_103-safe).
// Feature/kv/att in fp32 SIMT. All scratch in __device__ globals.
// ---------------------------------------------------------------------------

#define B_    4
#define S_    4096
#define DM    1024
#define H_    16
#define DH    64
#define RR    256
#define MROWS (B_*S_)        // 16384
#define NROWS (B_*S_*H_)     // 262144
#define BH    (B_*H_)        // 64
#define SPLIT 8
#define SCH   (S_/SPLIT)     // 512

#define RATIO 0.0625f                 // 1/sqrt(R)
#define CNORM 0.35355339059327373f    // Dh^{-1/4}

// ------------------------------ scratch ------------------------------------
__device__ float g_q[MROWS*DM];
__device__ float g_k[MROWS*DM];
__device__ float g_v[MROWS*DM];
__device__ float g_att[MROWS*DM];
__device__ float g_qhat[NROWS*RR];
__device__ float g_u[NROWS*RR];
__device__ float g_den[NROWS];
__device__ float g_kvp[SPLIT*BH*RR*DH];
__device__ float g_kvf[BH*RR*DH];
__device__ float g_u1p[SPLIT*BH*RR];
__device__ float g_v1p[SPLIT*BH*DH];
__device__ float g_k1[BH*RR];
__device__ float g_v1[BH*DH];
__device__ float g_kmax;
// bf16 split buffers (reused across the 4 GEMMs)
__device__ __nv_bfloat16 g_ah[MROWS*DM];
__device__ __nv_bfloat16 g_al[MROWS*DM];
__device__ __nv_bfloat16 g_wh[DM*DM];
__device__ __nv_bfloat16 g_wl[DM*DM];

extern __shared__ float dynsm[];

// ------------------------- FMA-pipe exp (no MUFU) --------------------------
__device__ __forceinline__ float fexp(float x)
{
    x = fminf(fmaxf(x, -87.0f), 87.0f);
    float z = x * 1.4426950408889634f;
    float t = z + 12582912.0f;
    int   n = __float_as_int(t) - 0x4B400000;
    float f = z - (t - 12582912.0f);
    float p = 1.3333558e-3f;
    p = fmaf(p, f, 9.6181291e-3f);
    p = fmaf(p, f, 5.5504109e-2f);
    p = fmaf(p, f, 2.4022651e-1f);
    p = fmaf(p, f, 6.9314718e-1f);
    p = fmaf(p, f, 1.0f);
    return p * __int_as_float((n + 127) << 23);
}

__device__ __forceinline__ void atomicMaxF(float* addr, float v)
{
    int* ia = (int*)addr;
    int old = *ia;
    while (__int_as_float(old) < v) {
        int assumed = old;
        old = atomicCAS(ia, assumed, __float_as_int(v));
        if (old == assumed) break;
    }
}

__global__ void k_init() { g_kmax = -3.0e38f; }

// ----------------------- PTX helpers (compute_103-safe) ---------------------
__device__ __forceinline__ uint32_t s2u(const void* p)
{
    uint32_t a;
    asm("{ .reg .u64 t; cvta.to.shared.u64 t, %1; cvt.u32.u64 %0, t; }"
        : "=r"(a) : "l"(p));
    return a;
}
__device__ __forceinline__ void cp16(uint32_t s, const void* g)
{
    asm volatile("cp.async.cg.shared.global [%0], [%1], 16;"
                 :: "r"(s), "l"(g));
}
__device__ __forceinline__ void ldm4(uint32_t* r, uint32_t addr)
{
    asm volatile("ldmatrix.sync.aligned.m8n8.x4.shared.b16 {%0,%1,%2,%3}, [%4];"
                 : "=r"(r[0]), "=r"(r[1]), "=r"(r[2]), "=r"(r[3]) : "r"(addr));
}
__device__ __forceinline__ void mma16816(float* c, const uint32_t* a,
                                         const uint32_t* b)
{
    asm volatile("mma.sync.aligned.m16n8k16.row.col.f32.bf16.bf16.f32 "
                 "{%0,%1,%2,%3}, {%4,%5,%6,%7}, {%8,%9}, {%0,%1,%2,%3};"
                 : "+f"(c[0]), "+f"(c[1]), "+f"(c[2]), "+f"(c[3])
                 : "r"(a[0]), "r"(a[1]), "r"(a[2]), "r"(a[3]),
                   "r"(b[0]), "r"(b[1]));
}

// ------------------------ split-bf16 conversion -----------------------------
__global__ __launch_bounds__(256)
void k_cvt_act(const float4* __restrict__ X, uint2* __restrict__ Hh,
               uint2* __restrict__ Hl)
{
    const int i = blockIdx.x * 256 + threadIdx.x;
    float4 x = X[i];
    uint32_t hx = __bfloat16_as_ushort(__float2bfloat16(x.x));
    uint32_t hy = __bfloat16_as_ushort(__float2bfloat16(x.y));
    uint32_t hz = __bfloat16_as_ushort(__float2bfloat16(x.z));
    uint32_t hw = __bfloat16_as_ushort(__float2bfloat16(x.w));
    float rx = x.x - __bfloat162float(__ushort_as_bfloat16((unsigned short)hx));
    float ry = x.y - __bfloat162float(__ushort_as_bfloat16((unsigned short)hy));
    float rz = x.z - __bfloat162float(__ushort_as_bfloat16((unsigned short)hz));
    float rw = x.w - __bfloat162float(__ushort_as_bfloat16((unsigned short)hw));
    uint32_t lx = __bfloat16_as_ushort(__float2bfloat16(rx));
    uint32_t ly = __bfloat16_as_ushort(__float2bfloat16(ry));
    uint32_t lz = __bfloat16_as_ushort(__float2bfloat16(rz));
    uint32_t lw = __bfloat16_as_ushort(__float2bfloat16(rw));
    uint2 h; h.x = hx | (hy << 16); h.y = hz | (hw << 16);
    uint2 l; l.x = lx | (ly << 16); l.y = lz | (lw << 16);
    Hh[i] = h; Hl[i] = l;
}

// W[k][n] -> Th/Tl[n][k] (transpose + split), 32x32 tiles
__global__ void k_cvt_wt(const float* __restrict__ W, __nv_bfloat16* __restrict__ Th,
                         __nv_bfloat16* __restrict__ Tl)
{
    __shared__ float t[32][33];
    const int n0 = blockIdx.x * 32, k0 = blockIdx.y * 32;
    const int tx = threadIdx.x, ty = threadIdx.y;
    #pragma unroll
    for (int j = 0; j < 32; j += 8)
        t[ty + j][tx] = W[(size_t)(k0 + ty + j) * DM + n0 + tx];
    __syncthreads();
    #pragma unroll
    for (int j = 0; j < 32; j += 8) {
        float v = t[tx][ty + j];
        __nv_bfloat16 h = __float2bfloat16(v);
        Th[(size_t)(n0 + ty + j) * DM + k0 + tx] = h;
        Tl[(size_t)(n0 + ty + j) * DM + k0 + tx] =
            __float2bfloat16(v - __bfloat162float(h));
    }
}

// -------------- HMMA GEMM: C[16384,1024] = A @ B^T (+bias) ------------------
// A hi/lo: [M][K] bf16. B hi/lo: [N][K] bf16 (pre-transposed weights).
// 128x128 tile/CTA, 256 thr (8 warps: 2m x 4n, 64x32 per warp), K-chunk 32,
// 3-stage cp.async pipeline, ldmatrix from 80B-stride rows (conflict-free).
#define MCHK  32
#define NCHK  (DM / MCHK)          // 32 chunks
#define MAT   (128 * 80)           // one 128x32 bf16 tile, 80B row stride
#define STG   (4 * MAT)            // Ah, Al, Bh, Bl
#define MM_SMEM (3 * STG)          // 122880 B

__global__ __launch_bounds__(256)
void k_mm(const __nv_bfloat16* __restrict__ Ah, const __nv_bfloat16* __restrict__ Al,
          const __nv_bfloat16* __restrict__ Bh, const __nv_bfloat16* __restrict__ Bl,
          const float* __restrict__ bias, float* __restrict__ C)
{
    const uint32_t smb = s2u(dynsm);
    const int tid = threadIdx.x, wid = tid >> 5, lane = tid & 31;
    const int bx = blockIdx.x, by = blockIdx.y;
    const int wm = wid & 1, wn = wid >> 1;

    const __nv_bfloat16* gbase[4];
    gbase[0] = Ah + (size_t)(by * 128) * DM;
    gbase[1] = Al + (size_t)(by * 128) * DM;
    gbase[2] = Bh + (size_t)(bx * 128) * DM;
    gbase[3] = Bl + (size_t)(bx * 128) * DM;

    // per-thread loader coords: 8 x 16B per chunk (2048 total / 256 thr)
    int lmat[8], lrow[8], lq[8];
    #pragma unroll
    for (int t = 0; t < 8; t++) {
        int idx = tid + t * 256;
        lmat[t] = idx >> 9;
        lrow[t] = (idx >> 2) & 127;
        lq[t]   = idx & 3;
    }

    auto issue = [&](int c, int s) {
        const int k0 = c * MCHK;
        #pragma unroll
        for (int t = 0; t < 8; t++) {
            const __nv_bfloat16* gp = gbase[lmat[t]] + (size_t)lrow[t] * DM
                                      + k0 + lq[t] * 8;
            uint32_t sa = smb + s * STG + lmat[t] * MAT + lrow[t] * 80 + lq[t] * 16;
            cp16(sa, gp);
        }
        asm volatile("cp.async.commit_group;");
    };

    issue(0, 0);
    issue(1, 1);
    issue(2, 2);

    // ldmatrix lane addressing
    const int part = lane >> 3, l8 = lane & 7;
    const int aRow = (part & 1) * 8 + l8, aCol = (part >> 1) * 8;
    const int bRow = (part >> 1) * 8 + l8, bCol = (part & 1) * 8;

    float acc[4][4][4] = {};

    for (int c = 0; c < NCHK; c++) {
        const int s = c % 3;
        asm volatile("cp.async.wait_group 2;");
        __syncthreads();

        const uint32_t sb = smb + s * STG;
        #pragma unroll
        for (int kk = 0; kk < 2; kk++) {
            uint32_t ah[16], al[16], bh[8], bl[8];
            #pragma unroll
            for (int mi = 0; mi < 4; mi++) {
                uint32_t off = (uint32_t)((wm * 64 + mi * 16 + aRow) * 80
                                          + (kk * 16 + aCol) * 2);
                ldm4(&ah[mi * 4], sb + off);
                ldm4(&al[mi * 4], sb + MAT + off);
            }
            #pragma unroll
            for (int f = 0; f < 2; f++) {
                uint32_t off = (uint32_t)((wn * 32 + f * 16 + bRow) * 80
                                          + (kk * 16 + bCol) * 2);
                ldm4(&bh[f * 4], sb + 2 * MAT + off);
                ldm4(&bl[f * 4], sb + 3 * MAT + off);
            }
            // b frag (ni): regs { (ni&1? +2 : 0) within x4 group ni>>1 }
            #pragma unroll
            for (int mi = 0; mi < 4; mi++)
                #pragma unroll
                for (int ni = 0; ni < 4; ni++) {
                    uint32_t* bph = &bh[(ni >> 1) * 4 + (ni & 1) * 2];
                    uint32_t* bpl = &bl[(ni >> 1) * 4 + (ni & 1) * 2];
                    mma16816(acc[mi][ni], &ah[mi * 4], bph);
                    mma16816(acc[mi][ni], &ah[mi * 4], bpl);
                    mma16816(acc[mi][ni], &al[mi * 4], bph);
                }
        }
        __syncthreads();
        if (c + 3 < NCHK) issue(c + 3, s);
    }

    // epilogue: frag (mi,ni): rows by*128+wm*64+mi*16+{g, g+8}, g = lane>>2
    // cols bx*128 + wn*32 + ni*8 + (lane&3)*2
    const int g = lane >> 2, cc = (lane & 3) * 2;
    #pragma unroll
    for (int mi = 0; mi < 4; mi++) {
        const int r0 = by * 128 + wm * 64 + mi * 16 + g;
        #pragma unroll
        for (int ni = 0; ni < 4; ni++) {
            const int col = bx * 128 + wn * 32 + ni * 8 + cc;
            const float b0 = bias[col], b1 = bias[col + 1];
            float2 o0, o1;
            o0.x = acc[mi][ni][0] + b0; o0.y = acc[mi][ni][1] + b1;
            o1.x = acc[mi][ni][2] + b0; o1.y = acc[mi][ni][3] + b1;
            *(float2*)(C + (size_t)r0 * DM + col)       = o0;
            *(float2*)(C + (size_t)(r0 + 8) * DM + col) = o1;
        }
    }
}

// ------------------- FAVOR+ feature kernel (q or k) -------------------------
#define FEAT_SMEM ((64*256 + 8*4*64) * 4)

template <bool IS_Q>
__global__ __launch_bounds__(256)
void k_feat(const float* __restrict__ X, const float* __restrict__ proj,
            float* __restrict__ out, const float* __restrict__ k1,
            float* __restrict__ den)
{
    float* sm = dynsm;
    float* projT = sm;
    float* sq    = sm + 64 * 256;
    const int tid = threadIdx.x;
    const int w = tid >> 5, l = tid & 31;

    for (int i = tid; i < 64 * 256; i += 256) {
        int k = i >> 8, r = i & 255;
        projT[i] = CNORM * proj[r * 64 + k];
    }
    __syncthreads();

    const float4* pT = (const float4*)projT;
    float* sqw = sq + w * 4 * 64;
    float wmax = -3.0e38f;
    const int jrow = l >> 3;
    const int off  = (l & 7) * 8;
    const int base = blockIdx.x * 512 + w * 64;

    for (int it = 0; it < 16; it++) {
        const int n0 = base + it * 4;
        const float* xp = X + (n0 + jrow) * 64 + off;
        float4 xa = *(const float4*)xp;
        float4 xb = *(const float4*)(xp + 4);
        float ss = xa.x*xa.x + xa.y*xa.y + xa.z*xa.z + xa.w*xa.w
                 + xb.x*xb.x + xb.y*xb.y + xb.z*xb.z + xb.w*xb.w;
        ss += __shfl_xor_sync(0xffffffffu, ss, 1);
        ss += __shfl_xor_sync(0xffffffffu, ss, 2);
        ss += __shfl_xor_sync(0xffffffffu, ss, 4);
        float diagl = 0.0625f * ss;
        float diag[4];
        #pragma unroll
        for (int j = 0; j < 4; j++)
            diag[j] = __shfl_sync(0xffffffffu, diagl, j * 8);

        __syncwarp();
        *(float4*)&sqw[jrow * 64 + off]     = xa;
        *(float4*)&sqw[jrow * 64 + off + 4] = xb;
        __syncwarp();

        float4 a0[4] = {}, a1[4] = {};
        #pragma unroll 2
        for (int k = 0; k < 64; k++) {
            float4 p0 = pT[k * 64 + l];
            float4 p1 = pT[k * 64 + 32 + l];
            #pragma unroll
            for (int j = 0; j < 4; j++) {
                float qk = sqw[j * 64 + k];
                a0[j].x = fmaf(qk, p0.x, a0[j].x);
                a0[j].y = fmaf(qk, p0.y, a0[j].y);
                a0[j].z = fmaf(qk, p0.z, a0[j].z);
                a0[j].w = fmaf(qk, p0.w, a0[j].w);
                a1[j].x = fmaf(qk, p1.x, a1[j].x);
                a1[j].y = fmaf(qk, p1.y, a1[j].y);
                a1[j].z = fmaf(qk, p1.z, a1[j].z);
                a1[j].w = fmaf(qk, p1.w, a1[j].w);
            }
        }
        #pragma unroll
        for (int j = 0; j < 4; j++) {
            const int n = n0 + j;
            float* op = out + n * 256 + 4 * l;
            float lm = fmaxf(fmaxf(fmaxf(a0[j].x, a0[j].y), fmaxf(a0[j].z, a0[j].w)),
                             fmaxf(fmaxf(a1[j].x, a1[j].y), fmaxf(a1[j].z, a1[j].w)));
            if (IS_Q) {
                #pragma unroll
                for (int o = 16; o > 0; o >>= 1)
                    lm = fmaxf(lm, __shfl_xor_sync(0xffffffffu, lm, o));
                const float sub = diag[j] + lm;
                float4 w0, w1;
                w0.x = RATIO * (fexp(a0[j].x - sub) + 1e-4f);
                w0.y = RATIO * (fexp(a0[j].y - sub) + 1e-4f);
                w0.z = RATIO * (fexp(a0[j].z - sub) + 1e-4f);
                w0.w = RATIO * (fexp(a0[j].w - sub) + 1e-4f);
                w1.x = RATIO * (fexp(a1[j].x - sub) + 1e-4f);
                w1.y = RATIO * (fexp(a1[j].y - sub) + 1e-4f);
                w1.z = RATIO * (fexp(a1[j].z - sub) + 1e-4f);
                w1.w = RATIO * (fexp(a1[j].w - sub) + 1e-4f);
                *(float4*)op         = w0;
                *(float4*)(op + 128) = w1;
                const int bh = ((n >> 16) << 4) | (n & 15);
                const float* kp = k1 + bh * 256 + 4 * l;
                float4 c0 = *(const float4*)kp;
                float4 c1 = *(const float4*)(kp + 128);
                float dp = w0.x*c0.x + w0.y*c0.y + w0.z*c0.z + w0.w*c0.w
                         + w1.x*c1.x + w1.y*c1.y + w1.z*c1.z + w1.w*c1.w;
                #pragma unroll
                for (int o = 16; o > 0; o >>= 1)
                    dp += __shfl_xor_sync(0xffffffffu, dp, o);
                if (l == 0) den[n] = dp;
            } else {
                wmax = fmaxf(wmax, lm);
                const float sub = diag[j];
                float4 w0, w1;
                w0.x = fexp(a0[j].x - sub);
                w0.y = fexp(a0[j].y - sub);
                w0.z = fexp(a0[j].z - sub);
                w0.w = fexp(a0[j].w - sub);
                w1.x = fexp(a1[j].x - sub);
                w1.y = fexp(a1[j].y - sub);
                w1.z = fexp(a1[j].z - sub);
                w1.w = fexp(a1[j].w - sub);
                *(float4*)op         = w0;
                *(float4*)(op + 128) = w1;
            }
        }
    }
    if (!IS_Q) {
        #pragma unroll
        for (int o = 16; o > 0; o >>= 1)
            wmax = fmaxf(wmax, __shfl_xor_sync(0xffffffffu, wmax, o));
        __syncthreads();
        if (l == 0) sm[w] = wmax;
        __syncthreads();
        if (tid == 0) {
            float m = sm[0];
            #pragma unroll
            for (int i = 1; i < 8; i++) m = fmaxf(m, sm[i]);
            atomicMaxF(&g_kmax, m);
        }
    }
}

// --------- kv partials: per (bh, S-chunk) compute u^T @ v [256 x 64] --------
__global__ __launch_bounds__(256)
void k_kv()
{
    __shared__ float Us[16][256];
    __shared__ float Vs[16][64];
    const int bh = blockIdx.x, c = blockIdx.y;
    const int b = bh >> 4, h = bh & 15;
    const int tid = threadIdx.x;
    const int ls = tid >> 4, lr = (tid & 15) * 16;
    const int lv = (tid & 15) * 4;
    const int tr = (tid >> 3) * 8, tv = (tid & 7) * 8;
    const float* ub = g_u + ((b * S_ + c * SCH) * H_ + h) * RR;
    const float* vb = g_v + (b * S_ + c * SCH) * DM + h * DH;

    float acc[8][8] = {};
    float uacc = 0.f, vacc = 0.f;
    for (int s0 = 0; s0 < SCH; s0 += 16) {
        const float* up = ub + (s0 + ls) * (H_ * RR) + lr;
        *(float4*)&Us[ls][lr]      = *(const float4*)(up);
        *(float4*)&Us[ls][lr + 4]  = *(const float4*)(up + 4);
        *(float4*)&Us[ls][lr + 8]  = *(const float4*)(up + 8);
        *(float4*)&Us[ls][lr + 12] = *(const float4*)(up + 12);
        *(float4*)&Vs[ls][lv] = *(const float4*)(vb + (s0 + ls) * DM + lv);
        __syncthreads();
        #pragma unroll
        for (int s = 0; s < 16; s++) {
            float ua[8], va[8];
            *(float4*)&ua[0] = *(const float4*)&Us[s][tr];
            *(float4*)&ua[4] = *(const float4*)&Us[s][tr + 4];
            *(float4*)&va[0] = *(const float4*)&Vs[s][tv];
            *(float4*)&va[4] = *(const float4*)&Vs[s][tv + 4];
            #pragma unroll
            for (int i = 0; i < 8; i++)
                #pragma unroll
                for (int j = 0; j < 8; j++)
                    acc[i][j] = fmaf(ua[i], va[j], acc[i][j]);
            uacc += Us[s][tid];
            if (tid < 64) vacc += Vs[s][tid];
        }
        __syncthreads();
    }
    const int pb = c * BH + bh;
    float* kp = g_kvp + pb * (RR * DH);
    #pragma unroll
    for (int i = 0; i < 8; i++) {
        *(float4*)&kp[(tr + i) * DH + tv]     = *(float4*)&acc[i][0];
        *(float4*)&kp[(tr + i) * DH + tv + 4] = *(float4*)&acc[i][4];
    }
    g_u1p[pb * RR + tid] = uacc;
    if (tid < 64) g_v1p[pb * DH + tid] = vacc;
}

__global__ void k_red()
{
    const int bh = blockIdx.x, t = threadIdx.x;
    const float a = RATIO * fexp(-g_kmax);
    float s = 0.f;
    #pragma unroll
    for (int c = 0; c < SPLIT; c++) s += g_u1p[(c * BH + bh) * RR + t];
    g_k1[bh * RR + t] = a * s + RATIO * 1e-4f * (float)S_;
    if (t < DH) {
        float vs = 0.f;
        #pragma unroll
        for (int c = 0; c < SPLIT; c++) vs += g_v1p[(c * BH + bh) * DH + t];
        g_v1[bh * DH + t] = vs;
    }
}

__global__ void k_kvred()
{
    const int bh = blockIdx.x, r = blockIdx.y, v = threadIdx.x;
    const float a = RATIO * fexp(-g_kmax);
    float s = 0.f;
    #pragma unroll
    for (int c = 0; c < SPLIT; c++)
        s += g_kvp[((c * BH + bh) * RR + r) * DH + v];
    g_kvf[(bh * RR + r) * DH + v] = a * s + RATIO * 1e-4f * g_v1[bh * DH + v];
}

// ----- attention out: per (bh, s-chunk 128): qhat[128,256] @ kvf[256,64] ----
__global__ __launch_bounds__(256)
void k_att()
{
    __shared__ float As[16][128];
    __shared__ float Bs[16][64];
    const int bh = blockIdx.x, sc = blockIdx.y;
    const int b = bh >> 4, h = bh & 15;
    const int tid = threadIdx.x;
    const int srow = tid >> 1, kcol = (tid & 1) * 8;
    const int krow = tid >> 4, vcol = (tid & 15) * 4;
    const int ts = (tid >> 3) * 4, tv = (tid & 7) * 8;
    const int s_base = sc * 128;
    const float* qb  = g_qhat + ((b * S_ + s_base) * H_ + h) * RR;
    const float* kvb = g_kvf + bh * (RR * DH);

    float acc[4][8] = {};
    for (int k0 = 0; k0 < RR; k0 += 16) {
        const float* qp = qb + srow * (H_ * RR) + k0 + kcol;
        float4 qa = *(const float4*)qp;
        float4 qc = *(const float4*)(qp + 4);
        As[kcol + 0][srow] = qa.x;
        As[kcol + 1][srow] = qa.y;
        As[kcol + 2][srow] = qa.z;
        As[kcol + 3][srow] = qa.w;
        As[kcol + 4][srow] = qc.x;
        As[kcol + 5][srow] = qc.y;
        As[kcol + 6][srow] = qc.z;
        As[kcol + 7][srow] = qc.w;
        *(float4*)&Bs[krow][vcol] = *(const float4*)(kvb + (k0 + krow) * DH + vcol);
        __syncthreads();
        #pragma unroll
        for (int k = 0; k < 16; k++) {
            float a4[4], b8[8];
            a4[0] = As[k][ts + 0];
            a4[1] = As[k][ts + 1];
            a4[2] = As[k][ts + 2];
            a4[3] = As[k][ts + 3];
            *(float4*)&b8[0] = *(const float4*)&Bs[k][tv];
            *(float4*)&b8[4] = *(const float4*)&Bs[k][tv + 4];
            #pragma unroll
            for (int i = 0; i < 4; i++)
                #pragma unroll
                for (int j = 0; j < 8; j++)
                    acc[i][j] = fmaf(a4[i], b8[j], acc[i][j]);
        }
        __syncthreads();
    }
    #pragma unroll
    for (int i = 0; i < 4; i++) {
        const int s = s_base + ts + i;
        const int n = (b * S_ + s) * H_ + h;
        const float inv = 1.0f / g_den[n];
        float* op = g_att + (b * S_ + s) * DM + h * DH + tv;
        float4 o0, o1;
        o0.x = acc[i][0] * inv; o0.y = acc[i][1] * inv;
        o0.z = acc[i][2] * inv; o0.w = acc[i][3] * inv;
        o1.x = acc[i][4] * inv; o1.y = acc[i][5] * inv;
        o1.z = acc[i][6] * inv; o1.w = acc[i][7] * inv;
        *(float4*)op       = o0;
        *(float4*)(op + 4) = o1;
    }
}

// ---------------------------------------------------------------------------
extern "C" void kernel_launch(void* const* d_in, const int* in_sizes, int n_in,
                              void* d_out, int out_size)
{
    const float* query = (const float*)d_in[0];
    const float* key   = (const float*)d_in[1];
    const float* value = (const float*)d_in[2];
    const float* Wq    = (const float*)d_in[3];
    const float* bq    = (const float*)d_in[4];
    const float* Wk    = (const float*)d_in[5];
    const float* bk    = (const float*)d_in[6];
    const float* Wv    = (const float*)d_in[7];
    const float* bv    = (const float*)d_in[8];
    const float* Wo    = (const float*)d_in[9];
    const float* bo    = (const float*)d_in[10];
    const float* proj  = (const float*)d_in[11];
    float* out = (float*)d_out;

    void *pq, *pk, *pv, *pa, *pqh, *pu, *pk1, *pden, *pah, *pal, *pwh, *pwl;
    cudaGetSymbolAddress(&pq,  g_q);
    cudaGetSymbolAddress(&pk,  g_k);
    cudaGetSymbolAddress(&pv,  g_v);
    cudaGetSymbolAddress(&pa,  g_att);
    cudaGetSymbolAddress(&pqh, g_qhat);
    cudaGetSymbolAddress(&pu,  g_u);
    cudaGetSymbolAddress(&pk1, g_k1);
    cudaGetSymbolAddress(&pden, g_den);
    cudaGetSymbolAddress(&pah, g_ah);
    cudaGetSymbolAddress(&pal, g_al);
    cudaGetSymbolAddress(&pwh, g_wh);
    cudaGetSymbolAddress(&pwl, g_wl);

    cudaFuncSetAttribute(k_feat<true>,  cudaFuncAttributeMaxDynamicSharedMemorySize, FEAT_SMEM);
    cudaFuncSetAttribute(k_feat<false>, cudaFuncAttributeMaxDynamicSharedMemorySize, FEAT_SMEM);
    cudaFuncSetAttribute(k_mm, cudaFuncAttributeMaxDynamicSharedMemorySize, MM_SMEM);

    __nv_bfloat16* ah = (__nv_bfloat16*)pah;
    __nv_bfloat16* al = (__nv_bfloat16*)pal;
    __nv_bfloat16* wh = (__nv_bfloat16*)pwh;
    __nv_bfloat16* wl = (__nv_bfloat16*)pwl;

    const int CVT_G = MROWS * DM / 4 / 256;     // 16384
    const dim3 WT_G(DM / 32, DM / 32);          // (32, 32)
    const dim3 WT_B(32, 8);
    const dim3 MM_G(DM / 128, MROWS / 128);     // (8, 128)

    k_init<<<1, 1>>>();

    // Q = query @ Wq + bq
    k_cvt_act<<<CVT_G, 256>>>((const float4*)query, (uint2*)ah, (uint2*)al);
    k_cvt_wt<<<WT_G, WT_B>>>(Wq, wh, wl);
    k_mm<<<MM_G, 256, MM_SMEM>>>(ah, al, wh, wl, bq, (float*)pq);
    // K = key @ Wk + bk
    k_cvt_act<<<CVT_G, 256>>>((const float4*)key, (uint2*)ah, (uint2*)al);
    k_cvt_wt<<<WT_G, WT_B>>>(Wk, wh, wl);
    k_mm<<<MM_G, 256, MM_SMEM>>>(ah, al, wh, wl, bk, (float*)pk);
    // V = value @ Wv + bv
    k_cvt_act<<<CVT_G, 256>>>((const float4*)value, (uint2*)ah, (uint2*)al);
    k_cvt_wt<<<WT_G, WT_B>>>(Wv, wh, wl);
    k_mm<<<MM_G, 256, MM_SMEM>>>(ah, al, wh, wl, bv, (float*)pv);

    // key feature path first (global max + k1 before fused q/denom kernel)
    k_feat<false><<<NROWS / 512, 256, FEAT_SMEM>>>((const float*)pk, proj,
                                                   (float*)pu, nullptr, nullptr);
    k_kv<<<dim3(BH, SPLIT), 256>>>();
    k_red<<<BH, 256>>>();
    k_kvred<<<dim3(BH, RR), DH>>>();

    k_feat<true><<<NROWS / 512, 256, FEAT_SMEM>>>((const float*)pq, proj,
                                                  (float*)pqh, (const float*)pk1,
                                                  (float*)pden);
    k_att<<<dim3(BH, S_ / 128), 256>>>();

    // out = att @ Wo + bo
    k_cvt_act<<<CVT_G, 256>>>((const float4*)pa, (uint2*)ah, (uint2*)al);
    k_cvt_wt<<<WT_G, WT_B>>>(Wo, wh, wl);
    k_mm<<<MM_G, 256, MM_SMEM>>>(ah, al, wh, wl, bo, out);
}

// round 7
// speedup vs baseline: 1.7502x; 1.0089x over previous
#include <cuda_runtime.h>
#include <cuda_bf16.h>
#include <cstdint>

// ---------------------------------------------------------------------------
// Performer attention. Fixed shapes: B=4, S=4096, Dm=1024, H=16, Dh=64, R=256
// Big GEMMs: split-bf16 (hi/lo) on mma.sync HMMA, 4-stage cp.async pipeline,
// 2 CTAs/SM. Feature/kv/att in fp32 SIMT. Scratch in __device__ globals.
// ---------------------------------------------------------------------------

#define B_    4
#define S_    4096
#define DM    1024
#define H_    16
#define DH    64
#define RR    256
#define MROWS (B_*S_)        // 16384
#define NROWS (B_*S_*H_)     // 262144
#define BH    (B_*H_)        // 64
#define SPLIT 8
#define SCH   (S_/SPLIT)     // 512

#define RATIO 0.0625f                 // 1/sqrt(R)
#define CNORM 0.35355339059327373f    // Dh^{-1/4}

// ------------------------------ scratch ------------------------------------
__device__ float g_q[MROWS*DM];
__device__ float g_k[MROWS*DM];
__device__ float g_v[MROWS*DM];
__device__ float g_qhat[NROWS*RR];
__device__ float g_u[NROWS*RR];
__device__ float g_den[NROWS];
__device__ float g_kvp[SPLIT*BH*RR*DH];
__device__ float g_kvf[BH*RR*DH];
__device__ float g_u1p[SPLIT*BH*RR];
__device__ float g_v1p[SPLIT*BH*DH];
__device__ float g_k1[BH*RR];
__device__ float g_v1[BH*DH];
__device__ float g_kmax;
// bf16 split buffers (reused across the 4 GEMMs)
__device__ __nv_bfloat16 g_ah[MROWS*DM];
__device__ __nv_bfloat16 g_al[MROWS*DM];
__device__ __nv_bfloat16 g_wh[DM*DM];
__device__ __nv_bfloat16 g_wl[DM*DM];

extern __shared__ float dynsm[];

// ------------------------- FMA-pipe exp (no MUFU) --------------------------
__device__ __forceinline__ float fexp(float x)
{
    x = fminf(fmaxf(x, -87.0f), 87.0f);
    float z = x * 1.4426950408889634f;
    float t = z + 12582912.0f;
    int   n = __float_as_int(t) - 0x4B400000;
    float f = z - (t - 12582912.0f);
    float p = 1.3333558e-3f;
    p = fmaf(p, f, 9.6181291e-3f);
    p = fmaf(p, f, 5.5504109e-2f);
    p = fmaf(p, f, 2.4022651e-1f);
    p = fmaf(p, f, 6.9314718e-1f);
    p = fmaf(p, f, 1.0f);
    return p * __int_as_float((n + 127) << 23);
}

__device__ __forceinline__ void atomicMaxF(float* addr, float v)
{
    int* ia = (int*)addr;
    int old = *ia;
    while (__int_as_float(old) < v) {
        int assumed = old;
        old = atomicCAS(ia, assumed, __float_as_int(v));
        if (old == assumed) break;
    }
}

__global__ void k_init() { g_kmax = -3.0e38f; }

// ----------------------- PTX helpers (compute_103-safe) ---------------------
__device__ __forceinline__ uint32_t s2u(const void* p)
{
    uint32_t a;
    asm("{ .reg .u64 t; cvta.to.shared.u64 t, %1; cvt.u32.u64 %0, t; }"
        : "=r"(a) : "l"(p));
    return a;
}
__device__ __forceinline__ void cp16(uint32_t s, const void* g)
{
    asm volatile("cp.async.cg.shared.global [%0], [%1], 16;"
                 :: "r"(s), "l"(g));
}
__device__ __forceinline__ void ldm4(uint32_t* r, uint32_t addr)
{
    asm volatile("ldmatrix.sync.aligned.m8n8.x4.shared.b16 {%0,%1,%2,%3}, [%4];"
                 : "=r"(r[0]), "=r"(r[1]), "=r"(r[2]), "=r"(r[3]) : "r"(addr));
}
__device__ __forceinline__ void mma16816(float* c, const uint32_t* a,
                                         const uint32_t* b)
{
    asm volatile("mma.sync.aligned.m16n8k16.row.col.f32.bf16.bf16.f32 "
                 "{%0,%1,%2,%3}, {%4,%5,%6,%7}, {%8,%9}, {%0,%1,%2,%3};"
                 : "+f"(c[0]), "+f"(c[1]), "+f"(c[2]), "+f"(c[3])
                 : "r"(a[0]), "r"(a[1]), "r"(a[2]), "r"(a[3]),
                   "r"(b[0]), "r"(b[1]));
}
__device__ __forceinline__ uint32_t pack2(float a, float b)
{
    return (uint32_t)__bfloat16_as_ushort(__float2bfloat16(a))
         | ((uint32_t)__bfloat16_as_ushort(__float2bfloat16(b)) << 16);
}

// ------------------------ split-bf16 conversion -----------------------------
__global__ __launch_bounds__(256)
void k_cvt_act(const float4* __restrict__ X, uint2* __restrict__ Hh,
               uint2* __restrict__ Hl)
{
    const int i = blockIdx.x * 256 + threadIdx.x;
    float4 x = X[i];
    uint32_t hx = __bfloat16_as_ushort(__float2bfloat16(x.x));
    uint32_t hy = __bfloat16_as_ushort(__float2bfloat16(x.y));
    uint32_t hz = __bfloat16_as_ushort(__float2bfloat16(x.z));
    uint32_t hw = __bfloat16_as_ushort(__float2bfloat16(x.w));
    float rx = x.x - __bfloat162float(__ushort_as_bfloat16((unsigned short)hx));
    float ry = x.y - __bfloat162float(__ushort_as_bfloat16((unsigned short)hy));
    float rz = x.z - __bfloat162float(__ushort_as_bfloat16((unsigned short)hz));
    float rw = x.w - __bfloat162float(__ushort_as_bfloat16((unsigned short)hw));
    uint32_t lx = __bfloat16_as_ushort(__float2bfloat16(rx));
    uint32_t ly = __bfloat16_as_ushort(__float2bfloat16(ry));
    uint32_t lz = __bfloat16_as_ushort(__float2bfloat16(rz));
    uint32_t lw = __bfloat16_as_ushort(__float2bfloat16(rw));
    uint2 h; h.x = hx | (hy << 16); h.y = hz | (hw << 16);
    uint2 l; l.x = lx | (ly << 16); l.y = lz | (lw << 16);
    Hh[i] = h; Hl[i] = l;
}

// W[k][n] -> Th/Tl[n][k] (transpose + split), 32x32 tiles
__global__ void k_cvt_wt(const float* __restrict__ W, __nv_bfloat16* __restrict__ Th,
                         __nv_bfloat16* __restrict__ Tl)
{
    __shared__ float t[32][33];
    const int n0 = blockIdx.x * 32, k0 = blockIdx.y * 32;
    const int tx = threadIdx.x, ty = threadIdx.y;
    #pragma unroll
    for (int j = 0; j < 32; j += 8)
        t[ty + j][tx] = W[(size_t)(k0 + ty + j) * DM + n0 + tx];
    __syncthreads();
    #pragma unroll
    for (int j = 0; j < 32; j += 8) {
        float v = t[tx][ty + j];
        __nv_bfloat16 h = __float2bfloat16(v);
        Th[(size_t)(n0 + ty + j) * DM + k0 + tx] = h;
        Tl[(size_t)(n0 + ty + j) * DM + k0 + tx] =
            __float2bfloat16(v - __bfloat162float(h));
    }
}

// -------------- HMMA GEMM: C[16384,1024] = A @ B^T (+bias) ------------------
// 128x128 tile/CTA, 256 thr (8 warps: 2m x 4n, 64x32/warp), K-chunk 16,
// 4-stage cp.async pipeline (96 KB), 2 CTAs/SM, 1 sync per chunk.
#define MCHK  16
#define NCHK  (DM / MCHK)          // 64 chunks
#define MATB  (128 * 48)           // one 128x16 bf16 tile, 48B row stride
#define STG   (4 * MATB)           // 24576 per stage (Ah, Al, Bh, Bl)
#define MM_SMEM (4 * STG)          // 98304 B

__global__ __launch_bounds__(256, 2)
void k_mm(const __nv_bfloat16* __restrict__ Ah, const __nv_bfloat16* __restrict__ Al,
          const __nv_bfloat16* __restrict__ Bh, const __nv_bfloat16* __restrict__ Bl,
          const float* __restrict__ bias, float* __restrict__ C)
{
    const uint32_t smb = s2u(dynsm);
    const int tid = threadIdx.x, wid = tid >> 5, lane = tid & 31;
    const int bx = blockIdx.x, by = blockIdx.y;
    const int wm = wid & 1, wn = wid >> 1;

    const __nv_bfloat16* gbase[4];
    gbase[0] = Ah + (size_t)(by * 128) * DM;
    gbase[1] = Al + (size_t)(by * 128) * DM;
    gbase[2] = Bh + (size_t)(bx * 128) * DM;
    gbase[3] = Bl + (size_t)(bx * 128) * DM;

    // loader: 4 x 16B per thread per chunk (1024 total)
    int lmat[4], lrow[4], lq[4];
    #pragma unroll
    for (int t = 0; t < 4; t++) {
        int idx = tid + t * 256;
        lmat[t] = idx >> 8;
        lrow[t] = (idx >> 1) & 127;
        lq[t]   = idx & 1;
    }

    auto issue = [&](int c) {
        const int k0 = c * MCHK;
        const uint32_t sb = smb + (uint32_t)(c & 3) * STG;
        #pragma unroll
        for (int t = 0; t < 4; t++) {
            const __nv_bfloat16* gp = gbase[lmat[t]] + (size_t)lrow[t] * DM
                                      + k0 + lq[t] * 8;
            cp16(sb + lmat[t] * MATB + lrow[t] * 48 + lq[t] * 16, gp);
        }
        asm volatile("cp.async.commit_group;");
    };

    issue(0); issue(1); issue(2);

    const int part = lane >> 3, l8 = lane & 7;
    const int aRow = (part & 1) * 8 + l8, aCol = (part >> 1) * 8;
    const int bRow = (part >> 1) * 8 + l8, bCol = (part & 1) * 8;
    uint32_t aoff[4], boff[2];
    #pragma unroll
    for (int mi = 0; mi < 4; mi++)
        aoff[mi] = (uint32_t)((wm * 64 + mi * 16 + aRow) * 48 + aCol * 2);
    #pragma unroll
    for (int f = 0; f < 2; f++)
        boff[f] = (uint32_t)((wn * 32 + f * 16 + bRow) * 48 + bCol * 2);

    float acc[4][4][4] = {};

    for (int c = 0; c < NCHK; c++) {
        asm volatile("cp.async.wait_group 2;");
        __syncthreads();
        if (c + 3 < NCHK) issue(c + 3);

        const uint32_t sb = smb + (uint32_t)(c & 3) * STG;
        uint32_t ah[16], al[16], bh[8], bl[8];
        #pragma unroll
        for (int mi = 0; mi < 4; mi++) {
            ldm4(&ah[mi * 4], sb + aoff[mi]);
            ldm4(&al[mi * 4], sb + MATB + aoff[mi]);
        }
        #pragma unroll
        for (int f = 0; f < 2; f++) {
            ldm4(&bh[f * 4], sb + 2 * MATB + boff[f]);
            ldm4(&bl[f * 4], sb + 3 * MATB + boff[f]);
        }
        #pragma unroll
        for (int mi = 0; mi < 4; mi++)
            #pragma unroll
            for (int ni = 0; ni < 4; ni++) {
                uint32_t* bph = &bh[(ni >> 1) * 4 + (ni & 1) * 2];
                uint32_t* bpl = &bl[(ni >> 1) * 4 + (ni & 1) * 2];
                mma16816(acc[mi][ni], &ah[mi * 4], bph);
                mma16816(acc[mi][ni], &ah[mi * 4], bpl);
                mma16816(acc[mi][ni], &al[mi * 4], bph);
            }
    }

    const int g = lane >> 2, cc = (lane & 3) * 2;
    #pragma unroll
    for (int mi = 0; mi < 4; mi++) {
        const int r0 = by * 128 + wm * 64 + mi * 16 + g;
        #pragma unroll
        for (int ni = 0; ni < 4; ni++) {
            const int col = bx * 128 + wn * 32 + ni * 8 + cc;
            const float b0 = bias[col], b1 = bias[col + 1];
            float2 o0, o1;
            o0.x = acc[mi][ni][0] + b0; o0.y = acc[mi][ni][1] + b1;
            o1.x = acc[mi][ni][2] + b0; o1.y = acc[mi][ni][3] + b1;
            *(float2*)(C + (size_t)r0 * DM + col)       = o0;
            *(float2*)(C + (size_t)(r0 + 8) * DM + col) = o1;
        }
    }
}

// ------------------- FAVOR+ feature kernel (q or k) -------------------------
#define FEAT_SMEM ((64*256 + 8*4*64) * 4)

template <bool IS_Q>
__global__ __launch_bounds__(256)
void k_feat(const float* __restrict__ X, const float* __restrict__ proj,
            float* __restrict__ out, const float* __restrict__ k1,
            float* __restrict__ den)
{
    float* sm = dynsm;
    float* projT = sm;
    float* sq    = sm + 64 * 256;
    const int tid = threadIdx.x;
    const int w = tid >> 5, l = tid & 31;

    for (int i = tid; i < 64 * 256; i += 256) {
        int k = i >> 8, r = i & 255;
        projT[i] = CNORM * proj[r * 64 + k];
    }
    __syncthreads();

    const float4* pT = (const float4*)projT;
    float* sqw = sq + w * 4 * 64;
    float wmax = -3.0e38f;
    const int jrow = l >> 3;
    const int off  = (l & 7) * 8;
    const int base = blockIdx.x * 512 + w * 64;

    for (int it = 0; it < 16; it++) {
        const int n0 = base + it * 4;
        const float* xp = X + (n0 + jrow) * 64 + off;
        float4 xa = *(const float4*)xp;
        float4 xb = *(const float4*)(xp + 4);
        float ss = xa.x*xa.x + xa.y*xa.y + xa.z*xa.z + xa.w*xa.w
                 + xb.x*xb.x + xb.y*xb.y + xb.z*xb.z + xb.w*xb.w;
        ss += __shfl_xor_sync(0xffffffffu, ss, 1);
        ss += __shfl_xor_sync(0xffffffffu, ss, 2);
        ss += __shfl_xor_sync(0xffffffffu, ss, 4);
        float diagl = 0.0625f * ss;
        float diag[4];
        #pragma unroll
        for (int j = 0; j < 4; j++)
            diag[j] = __shfl_sync(0xffffffffu, diagl, j * 8);

        __syncwarp();
        *(float4*)&sqw[jrow * 64 + off]     = xa;
        *(float4*)&sqw[jrow * 64 + off + 4] = xb;
        __syncwarp();

        float4 a0[4] = {}, a1[4] = {};
        #pragma unroll 2
        for (int k = 0; k < 64; k++) {
            float4 p0 = pT[k * 64 + l];
            float4 p1 = pT[k * 64 + 32 + l];
            #pragma unroll
            for (int j = 0; j < 4; j++) {
                float qk = sqw[j * 64 + k];
                a0[j].x = fmaf(qk, p0.x, a0[j].x);
                a0[j].y = fmaf(qk, p0.y, a0[j].y);
                a0[j].z = fmaf(qk, p0.z, a0[j].z);
                a0[j].w = fmaf(qk, p0.w, a0[j].w);
                a1[j].x = fmaf(qk, p1.x, a1[j].x);
                a1[j].y = fmaf(qk, p1.y, a1[j].y);
                a1[j].z = fmaf(qk, p1.z, a1[j].z);
                a1[j].w = fmaf(qk, p1.w, a1[j].w);
            }
        }
        #pragma unroll
        for (int j = 0; j < 4; j++) {
            const int n = n0 + j;
            float* op = out + n * 256 + 4 * l;
            float lm = fmaxf(fmaxf(fmaxf(a0[j].x, a0[j].y), fmaxf(a0[j].z, a0[j].w)),
                             fmaxf(fmaxf(a1[j].x, a1[j].y), fmaxf(a1[j].z, a1[j].w)));
            if (IS_Q) {
                #pragma unroll
                for (int o = 16; o > 0; o >>= 1)
                    lm = fmaxf(lm, __shfl_xor_sync(0xffffffffu, lm, o));
                const float sub = diag[j] + lm;
                float4 w0, w1;
                w0.x = RATIO * (fexp(a0[j].x - sub) + 1e-4f);
                w0.y = RATIO * (fexp(a0[j].y - sub) + 1e-4f);
                w0.z = RATIO * (fexp(a0[j].z - sub) + 1e-4f);
                w0.w = RATIO * (fexp(a0[j].w - sub) + 1e-4f);
                w1.x = RATIO * (fexp(a1[j].x - sub) + 1e-4f);
                w1.y = RATIO * (fexp(a1[j].y - sub) + 1e-4f);
                w1.z = RATIO * (fexp(a1[j].z - sub) + 1e-4f);
                w1.w = RATIO * (fexp(a1[j].w - sub) + 1e-4f);
                *(float4*)op         = w0;
                *(float4*)(op + 128) = w1;
                const int bh = ((n >> 16) << 4) | (n & 15);
                const float* kp = k1 + bh * 256 + 4 * l;
                float4 c0 = *(const float4*)kp;
                float4 c1 = *(const float4*)(kp + 128);
                float dp = w0.x*c0.x + w0.y*c0.y + w0.z*c0.z + w0.w*c0.w
                         + w1.x*c1.x + w1.y*c1.y + w1.z*c1.z + w1.w*c1.w;
                #pragma unroll
                for (int o = 16; o > 0; o >>= 1)
                    dp += __shfl_xor_sync(0xffffffffu, dp, o);
                if (l == 0) den[n] = dp;
            } else {
                wmax = fmaxf(wmax, lm);
                const float sub = diag[j];
                float4 w0, w1;
                w0.x = fexp(a0[j].x - sub);
                w0.y = fexp(a0[j].y - sub);
                w0.z = fexp(a0[j].z - sub);
                w0.w = fexp(a0[j].w - sub);
                w1.x = fexp(a1[j].x - sub);
                w1.y = fexp(a1[j].y - sub);
                w1.z = fexp(a1[j].z - sub);
                w1.w = fexp(a1[j].w - sub);
                *(float4*)op         = w0;
                *(float4*)(op + 128) = w1;
            }
        }
    }
    if (!IS_Q) {
        #pragma unroll
        for (int o = 16; o > 0; o >>= 1)
            wmax = fmaxf(wmax, __shfl_xor_sync(0xffffffffu, wmax, o));
        __syncthreads();
        if (l == 0) sm[w] = wmax;
        __syncthreads();
        if (tid == 0) {
            float m = sm[0];
            #pragma unroll
            for (int i = 1; i < 8; i++) m = fmaxf(m, sm[i]);
            atomicMaxF(&g_kmax, m);
        }
    }
}

// --------- kv partials: per (bh, S-chunk) compute u^T @ v [256 x 64] --------
__global__ __launch_bounds__(256)
void k_kv()
{
    __shared__ float Us[16][256];
    __shared__ float Vs[16][64];
    const int bh = blockIdx.x, c = blockIdx.y;
    const int b = bh >> 4, h = bh & 15;
    const int tid = threadIdx.x;
    const int ls = tid >> 4, lr = (tid & 15) * 16;
    const int lv = (tid & 15) * 4;
    const int tr = (tid >> 3) * 8, tv = (tid & 7) * 8;
    const float* ub = g_u + ((b * S_ + c * SCH) * H_ + h) * RR;
    const float* vb = g_v + (b * S_ + c * SCH) * DM + h * DH;

    float acc[8][8] = {};
    float uacc = 0.f, vacc = 0.f;
    for (int s0 = 0; s0 < SCH; s0 += 16) {
        const float* up = ub + (s0 + ls) * (H_ * RR) + lr;
        *(float4*)&Us[ls][lr]      = *(const float4*)(up);
        *(float4*)&Us[ls][lr + 4]  = *(const float4*)(up + 4);
        *(float4*)&Us[ls][lr + 8]  = *(const float4*)(up + 8);
        *(float4*)&Us[ls][lr + 12] = *(const float4*)(up + 12);
        *(float4*)&Vs[ls][lv] = *(const float4*)(vb + (s0 + ls) * DM + lv);
        __syncthreads();
        #pragma unroll
        for (int s = 0; s < 16; s++) {
            float ua[8], va[8];
            *(float4*)&ua[0] = *(const float4*)&Us[s][tr];
            *(float4*)&ua[4] = *(const float4*)&Us[s][tr + 4];
            *(float4*)&va[0] = *(const float4*)&Vs[s][tv];
            *(float4*)&va[4] = *(const float4*)&Vs[s][tv + 4];
            #pragma unroll
            for (int i = 0; i < 8; i++)
                #pragma unroll
                for (int j = 0; j < 8; j++)
                    acc[i][j] = fmaf(ua[i], va[j], acc[i][j]);
            uacc += Us[s][tid];
            if (tid < 64) vacc += Vs[s][tid];
        }
        __syncthreads();
    }
    const int pb = c * BH + bh;
    float* kp = g_kvp + pb * (RR * DH);
    #pragma unroll
    for (int i = 0; i < 8; i++) {
        *(float4*)&kp[(tr + i) * DH + tv]     = *(float4*)&acc[i][0];
        *(float4*)&kp[(tr + i) * DH + tv + 4] = *(float4*)&acc[i][4];
    }
    g_u1p[pb * RR + tid] = uacc;
    if (tid < 64) g_v1p[pb * DH + tid] = vacc;
}

__global__ void k_red()
{
    const int bh = blockIdx.x, t = threadIdx.x;
    const float a = RATIO * fexp(-g_kmax);
    float s = 0.f;
    #pragma unroll
    for (int c = 0; c < SPLIT; c++) s += g_u1p[(c * BH + bh) * RR + t];
    g_k1[bh * RR + t] = a * s + RATIO * 1e-4f * (float)S_;
    if (t < DH) {
        float vs = 0.f;
        #pragma unroll
        for (int c = 0; c < SPLIT; c++) vs += g_v1p[(c * BH + bh) * DH + t];
        g_v1[bh * DH + t] = vs;
    }
}

__global__ void k_kvred()
{
    const int bh = blockIdx.x, r = blockIdx.y, v = threadIdx.x;
    const float a = RATIO * fexp(-g_kmax);
    float s = 0.f;
    #pragma unroll
    for (int c = 0; c < SPLIT; c++)
        s += g_kvp[((c * BH + bh) * RR + r) * DH + v];
    g_kvf[(bh * RR + r) * DH + v] = a * s + RATIO * 1e-4f * g_v1[bh * DH + v];
}

// ----- attention out: qhat[128,256] @ kvf[256,64], /denom, emit bf16 hi/lo --
__global__ __launch_bounds__(256)
void k_att()
{
    __shared__ float As[16][128];
    __shared__ float Bs[16][64];
    const int bh = blockIdx.x, sc = blockIdx.y;
    const int b = bh >> 4, h = bh & 15;
    const int tid = threadIdx.x;
    const int srow = tid >> 1, kcol = (tid & 1) * 8;
    const int krow = tid >> 4, vcol = (tid & 15) * 4;
    const int ts = (tid >> 3) * 4, tv = (tid & 7) * 8;
    const int s_base = sc * 128;
    const float* qb  = g_qhat + ((b * S_ + s_base) * H_ + h) * RR;
    const float* kvb = g_kvf + bh * (RR * DH);

    float acc[4][8] = {};
    for (int k0 = 0; k0 < RR; k0 += 16) {
        const float* qp = qb + srow * (H_ * RR) + k0 + kcol;
        float4 qa = *(const float4*)qp;
        float4 qc = *(const float4*)(qp + 4);
        As[kcol + 0][srow] = qa.x;
        As[kcol + 1][srow] = qa.y;
        As[kcol + 2][srow] = qa.z;
        As[kcol + 3][srow] = qa.w;
        As[kcol + 4][srow] = qc.x;
        As[kcol + 5][srow] = qc.y;
        As[kcol + 6][srow] = qc.z;
        As[kcol + 7][srow] = qc.w;
        *(float4*)&Bs[krow][vcol] = *(const float4*)(kvb + (k0 + krow) * DH + vcol);
        __syncthreads();
        #pragma unroll
        for (int k = 0; k < 16; k++) {
            float a4[4], b8[8];
            a4[0] = As[k][ts + 0];
            a4[1] = As[k][ts + 1];
            a4[2] = As[k][ts + 2];
            a4[3] = As[k][ts + 3];
            *(float4*)&b8[0] = *(const float4*)&Bs[k][tv];
            *(float4*)&b8[4] = *(const float4*)&Bs[k][tv + 4];
            #pragma unroll
            for (int i = 0; i < 4; i++)
                #pragma unroll
                for (int j = 0; j < 8; j++)
                    acc[i][j] = fmaf(a4[i], b8[j], acc[i][j]);
        }
        __syncthreads();
    }
    #pragma unroll
    for (int i = 0; i < 4; i++) {
        const int s = s_base + ts + i;
        const int n = (b * S_ + s) * H_ + h;
        const float inv = 1.0f / g_den[n];
        const size_t ob = (size_t)(b * S_ + s) * DM + h * DH + tv;
        float v[8];
        #pragma unroll
        for (int j = 0; j < 8; j++) v[j] = acc[i][j] * inv;
        // split-bf16 emit: hi = bf16(v), lo = bf16(v - hi)
        float hi[8], lo[8];
        #pragma unroll
        for (int j = 0; j < 8; j++) {
            __nv_bfloat16 hb = __float2bfloat16(v[j]);
            hi[j] = __bfloat162float(hb);
            lo[j] = v[j] - hi[j];
        }
        uint4 ph, pl;
        ph.x = pack2(hi[0], hi[1]); ph.y = pack2(hi[2], hi[3]);
        ph.z = pack2(hi[4], hi[5]); ph.w = pack2(hi[6], hi[7]);
        pl.x = pack2(lo[0], lo[1]); pl.y = pack2(lo[2], lo[3]);
        pl.z = pack2(lo[4], lo[5]); pl.w = pack2(lo[6], lo[7]);
        *(uint4*)(g_ah + ob) = ph;
        *(uint4*)(g_al + ob) = pl;
    }
}

// ---------------------------------------------------------------------------
extern "C" void kernel_launch(void* const* d_in, const int* in_sizes, int n_in,
                              void* d_out, int out_size)
{
    const float* query = (const float*)d_in[0];
    const float* key   = (const float*)d_in[1];
    const float* value = (const float*)d_in[2];
    const float* Wq    = (const float*)d_in[3];
    const float* bq    = (const float*)d_in[4];
    const float* Wk    = (const float*)d_in[5];
    const float* bk    = (const float*)d_in[6];
    const float* Wv    = (const float*)d_in[7];
    const float* bv    = (const float*)d_in[8];
    const float* Wo    = (const float*)d_in[9];
    const float* bo    = (const float*)d_in[10];
    const float* proj  = (const float*)d_in[11];
    float* out = (float*)d_out;

    void *pq, *pk, *pv, *pqh, *pu, *pk1, *pden, *pah, *pal, *pwh, *pwl;
    cudaGetSymbolAddress(&pq,  g_q);
    cudaGetSymbolAddress(&pk,  g_k);
    cudaGetSymbolAddress(&pv,  g_v);
    cudaGetSymbolAddress(&pqh, g_qhat);
    cudaGetSymbolAddress(&pu,  g_u);
    cudaGetSymbolAddress(&pk1, g_k1);
    cudaGetSymbolAddress(&pden, g_den);
    cudaGetSymbolAddress(&pah, g_ah);
    cudaGetSymbolAddress(&pal, g_al);
    cudaGetSymbolAddress(&pwh, g_wh);
    cudaGetSymbolAddress(&pwl, g_wl);

    cudaFuncSetAttribute(k_feat<true>,  cudaFuncAttributeMaxDynamicSharedMemorySize, FEAT_SMEM);
    cudaFuncSetAttribute(k_feat<false>, cudaFuncAttributeMaxDynamicSharedMemorySize, FEAT_SMEM);
    cudaFuncSetAttribute(k_mm, cudaFuncAttributeMaxDynamicSharedMemorySize, MM_SMEM);

    __nv_bfloat16* ah = (__nv_bfloat16*)pah;
    __nv_bfloat16* al = (__nv_bfloat16*)pal;
    __nv_bfloat16* wh = (__nv_bfloat16*)pwh;
    __nv_bfloat16* wl = (__nv_bfloat16*)pwl;

    const int CVT_G = MROWS * DM / 4 / 256;     // 16384
    const dim3 WT_G(DM / 32, DM / 32);          // (32, 32)
    const dim3 WT_B(32, 8);
    const dim3 MM_G(DM / 128, MROWS / 128);     // (8, 128)

    k_init<<<1, 1>>>();

    // Q = query @ Wq + bq
    k_cvt_act<<<CVT_G, 256>>>((const float4*)query, (uint2*)ah, (uint2*)al);
    k_cvt_wt<<<WT_G, WT_B>>>(Wq, wh, wl);
    k_mm<<<MM_G, 256, MM_SMEM>>>(ah, al, wh, wl, bq, (float*)pq);
    // K = key @ Wk + bk
    k_cvt_act<<<CVT_G, 256>>>((const float4*)key, (uint2*)ah, (uint2*)al);
    k_cvt_wt<<<WT_G, WT_B>>>(Wk, wh, wl);
    k_mm<<<MM_G, 256, MM_SMEM>>>(ah, al, wh, wl, bk, (float*)pk);
    // V = value @ Wv + bv
    k_cvt_act<<<CVT_G, 256>>>((const float4*)value, (uint2*)ah, (uint2*)al);
    k_cvt_wt<<<WT_G, WT_B>>>(Wv, wh, wl);
    k_mm<<<MM_G, 256, MM_SMEM>>>(ah, al, wh, wl, bv, (float*)pv);

    // key feature path first (global max + k1 before fused q/denom kernel)
    k_feat<false><<<NROWS / 512, 256, FEAT_SMEM>>>((const float*)pk, proj,
                                                   (float*)pu, nullptr, nullptr);
    k_kv<<<dim3(BH, SPLIT), 256>>>();
    k_red<<<BH, 256>>>();
    k_kvred<<<dim3(BH, RR), DH>>>();

    k_feat<true><<<NROWS / 512, 256, FEAT_SMEM>>>((const float*)pq, proj,
                                                  (float*)pqh, (const float*)pk1,
                                                  (float*)pden);
    k_att<<<dim3(BH, S_ / 128), 256>>>();   // writes split-bf16 into g_ah/g_al

    // out = att @ Wo + bo
    k_cvt_wt<<<WT_G, WT_B>>>(Wo, wh, wl);
    k_mm<<<MM_G, 256, MM_SMEM>>>(ah, al, wh, wl, bo, out);
}